// round 13
// baseline (speedup 1.0000x reference)
#include <cuda_runtime.h>
#include <cstdint>

// Entmax (alpha=1.5) per row, B=2048 x N=32000 fp32.
// v12 = v9 pipeline (persistent CTA, single 125 KB smem buffer, in-place
// half-row TMA re-arm, chunked bulk copies) with a fused sweep:
//   per-warp threshold warpmax-1 (<= rowmax-1 <= tau_ref) lets each warp
//   filter its registers AND zero-store clean float4s IMMEDIATELY -- ~98% of
//   the output stream issues before the reduces/Newton and overlaps them.
//   Warp 0 prunes the candidate pool to > rowmax-1 (ballot compaction) and
//   runs Newton; deferred float4s (and a redo guard for the theoretical
//   tau_ref < warpmax-1 case) are written after tau publishes.

#define NC        32000
#define NVH_      4000           // float4 per half
#define TPB       1024
#define VPH       4
#define VPT       8
#define CAP       1024
#define NEG       (-1e30f)
#define HALF_BYTES 64000
#define CHUNKS    4
#define CHUNK_B   (HALF_BYTES / CHUNKS)

__device__ __forceinline__ uint32_t smem_u32(const void* p) {
    uint32_t a;
    asm("{ .reg .u64 t; cvta.to.shared.u64 t, %1; cvt.u32.u64 %0, t; }"
        : "=r"(a) : "l"(p));
    return a;
}
__device__ __forceinline__ void mbar_init(uint32_t a, uint32_t cnt) {
    asm volatile("mbarrier.init.shared.b64 [%0], %1;" :: "r"(a), "r"(cnt) : "memory");
}
__device__ __forceinline__ void mbar_expect_tx(uint32_t a, uint32_t bytes) {
    asm volatile("mbarrier.arrive.expect_tx.shared.b64 _, [%0], %1;"
                 :: "r"(a), "r"(bytes) : "memory");
}
__device__ __forceinline__ void tma_bulk_g2s(uint32_t dst, const void* src,
                                             uint32_t bytes, uint32_t mbar) {
    asm volatile(
        "cp.async.bulk.shared::cta.global.mbarrier::complete_tx::bytes "
        "[%0], [%1], %2, [%3];"
        :: "r"(dst), "l"(src), "r"(bytes), "r"(mbar) : "memory");
}
#define MBAR_WAIT(mbar, parity) do { \
    asm volatile( \
        "{\n\t.reg .pred P1;\n\t" \
        "WAIT_LOOP_%=:\n\t" \
        "mbarrier.try_wait.parity.acquire.cta.shared::cta.b64 P1, [%0], %1, 0x989680;\n\t" \
        "@P1 bra.uni WAIT_DONE_%=;\n\t" \
        "bra.uni WAIT_LOOP_%=;\n\t" \
        "WAIT_DONE_%=:\n\t}" \
        :: "r"(mbar), "r"(parity) : "memory"); \
} while (0)

__device__ __forceinline__ void arm_half(uint32_t mbar, uint32_t dst_base,
                                         const float* src_base) {
    mbar_expect_tx(mbar, HALF_BYTES);
    #pragma unroll
    for (int c = 0; c < CHUNKS; ++c) {
        tma_bulk_g2s(dst_base + c * CHUNK_B,
                     src_base + c * (CHUNK_B / 4), CHUNK_B, mbar);
    }
}

__device__ __forceinline__ float maxtree(float4 v) {
    return fmaxf(fmaxf(v.x, v.y), fmaxf(v.z, v.w));
}
__device__ __forceinline__ float4 ep4(float4 v, float t) {
    float a = fmaxf(v.x - t, 0.0f), b = fmaxf(v.y - t, 0.0f);
    float c = fmaxf(v.z - t, 0.0f), d = fmaxf(v.w - t, 0.0f);
    float4 o;
    o.x = a * sqrtf(a); o.y = b * sqrtf(b);
    o.z = c * sqrtf(c); o.w = d * sqrtf(d);
    return o;
}

__global__ __launch_bounds__(TPB, 1)
void entmax_kernel(const float* __restrict__ z, float* __restrict__ out,
                   int rows, int gstride) {
    __shared__ float    s_f[32];      // per-warp max
    __shared__ float    s_g[32];      // per-warp reject max (also fallback v)
    __shared__ int      s_i[32];      // fallback count partials
    __shared__ float    s_h[32];      // fallback sum partials
    __shared__ float    s_cand[CAP];
    __shared__ int      s_cnt;
    __shared__ float    s_tauref;
    __shared__ int      s_bK;
    __shared__ float    s_bS, s_bV;
    __shared__ uint64_t s_mb[2];
    extern __shared__ float4 s_buf[]; // 8000 float4 = 125 KB

    const int tid  = threadIdx.x;
    const int lane = tid & 31;
    const int wid  = tid >> 5;

    const uint32_t mbL = smem_u32(&s_mb[0]);
    const uint32_t mbH = smem_u32(&s_mb[1]);
    const uint32_t bufL = smem_u32(s_buf);
    const uint32_t bufH = bufL + HALF_BYTES;

    if (tid == 0) { mbar_init(mbL, 1); mbar_init(mbH, 1); s_cnt = 0; }
    __syncthreads();

    const int r0     = blockIdx.x;
    const int myrows = (r0 < rows) ? ((rows - r0 - 1) / gstride + 1) : 0;

    if (tid == 0 && myrows > 0) {
        const float* row0 = z + (long long)r0 * NC;
        arm_half(mbL, bufL, row0);
        arm_half(mbH, bufH, row0 + 4 * NVH_);
    }

    for (int ri = 0; ri < myrows; ++ri) {
        const int row = r0 + ri * gstride;
        const uint32_t par = (uint32_t)(ri & 1);
        const bool have_next = (ri + 1 < myrows);
        const float* nrow = z + (long long)(row + gstride) * NC;
        float4* orow = (float4*)(out + (long long)row * NC);
        const float4 z4 = make_float4(0.f, 0.f, 0.f, 0.f);

        float4 r[VPT];
        float vmax = NEG;
        uint32_t dmask = 0;

        // ================= LOWER HALF =================
        MBAR_WAIT(mbL, par);
        #pragma unroll
        for (int j = 0; j < VPH; ++j) {
            const int f = tid + j * TPB;
            r[j] = (f < NVH_) ? s_buf[f] : make_float4(NEG, NEG, NEG, NEG);
        }
        __syncthreads();                   // B1: lower reads done
        if (tid == 0) {
            asm volatile("fence.proxy.async.shared::cta;" ::: "memory");
            if (have_next) arm_half(mbL, bufL, nrow);
        }
        // warp max over lower half
        float wmL = NEG;
        #pragma unroll
        for (int j = 0; j < VPH; ++j) wmL = fmaxf(wmL, maxtree(r[j]));
        #pragma unroll
        for (int o = 16; o; o >>= 1)
            wmL = fmaxf(wmL, __shfl_xor_sync(0xffffffffu, wmL, o));
        const float thL = wmL - 1.0f;
        // filter + early zero-stores (lower)
        #pragma unroll
        for (int j = 0; j < VPH; ++j) {
            const int f = tid + j * TPB;
            if (f < NVH_) {
                const float4 v = r[j];
                const float m4 = maxtree(v);
                if (m4 > thL) {
                    dmask |= 1u << j;
                    float c;
                    c = v.x; if (c > thL) { int p = atomicAdd(&s_cnt, 1); if (p < CAP) s_cand[p] = c; } else vmax = fmaxf(vmax, c);
                    c = v.y; if (c > thL) { int p = atomicAdd(&s_cnt, 1); if (p < CAP) s_cand[p] = c; } else vmax = fmaxf(vmax, c);
                    c = v.z; if (c > thL) { int p = atomicAdd(&s_cnt, 1); if (p < CAP) s_cand[p] = c; } else vmax = fmaxf(vmax, c);
                    c = v.w; if (c > thL) { int p = atomicAdd(&s_cnt, 1); if (p < CAP) s_cand[p] = c; } else vmax = fmaxf(vmax, c);
                } else {
                    vmax = fmaxf(vmax, m4);
                    __stcs(&orow[f], z4);          // guaranteed zero
                }
            }
        }

        // ================= UPPER HALF =================
        MBAR_WAIT(mbH, par);
        #pragma unroll
        for (int j = 0; j < VPH; ++j) {
            const int f = tid + j * TPB;
            r[VPH + j] = (f < NVH_) ? s_buf[NVH_ + f] : make_float4(NEG, NEG, NEG, NEG);
        }
        __syncthreads();                   // B2: upper reads done
        if (tid == 0) {
            asm volatile("fence.proxy.async.shared::cta;" ::: "memory");
            if (have_next) arm_half(mbH, bufH, nrow + 4 * NVH_);
        }
        float wmU = NEG;
        #pragma unroll
        for (int j = 0; j < VPH; ++j) wmU = fmaxf(wmU, maxtree(r[VPH + j]));
        #pragma unroll
        for (int o = 16; o; o >>= 1)
            wmU = fmaxf(wmU, __shfl_xor_sync(0xffffffffu, wmU, o));
        const float thU = wmU - 1.0f;
        #pragma unroll
        for (int j = 0; j < VPH; ++j) {
            const int f = tid + j * TPB;
            if (f < NVH_) {
                const float4 v = r[VPH + j];
                const float m4 = maxtree(v);
                if (m4 > thU) {
                    dmask |= 1u << (VPH + j);
                    float c;
                    c = v.x; if (c > thU) { int p = atomicAdd(&s_cnt, 1); if (p < CAP) s_cand[p] = c; } else vmax = fmaxf(vmax, c);
                    c = v.y; if (c > thU) { int p = atomicAdd(&s_cnt, 1); if (p < CAP) s_cand[p] = c; } else vmax = fmaxf(vmax, c);
                    c = v.z; if (c > thU) { int p = atomicAdd(&s_cnt, 1); if (p < CAP) s_cand[p] = c; } else vmax = fmaxf(vmax, c);
                    c = v.w; if (c > thU) { int p = atomicAdd(&s_cnt, 1); if (p < CAP) s_cand[p] = c; } else vmax = fmaxf(vmax, c);
                } else {
                    vmax = fmaxf(vmax, m4);
                    __stcs(&orow[NVH_ + f], z4);   // guaranteed zero
                }
            }
        }

        // publish per-warp partials
        #pragma unroll
        for (int o = 16; o; o >>= 1)
            vmax = fmaxf(vmax, __shfl_xor_sync(0xffffffffu, vmax, o));
        if (lane == 0) { s_f[wid] = fmaxf(wmL, wmU); s_g[wid] = vmax; }
        __syncthreads();                   // B3: pool + partials visible
        const int cnt = s_cnt;
        float tau_ref;

        if (cnt <= CAP) {
            // ---- warp 0: rowmax, prune pool to > rowmax-1, Newton ----
            if (wid == 0) {
                float rm = s_f[lane];
                #pragma unroll
                for (int o = 16; o; o >>= 1)
                    rm = fmaxf(rm, __shfl_xor_sync(0xffffffffu, rm, o));
                const float tau0 = rm - 1.0f;
                float gv = s_g[lane];

                int m2 = 0;
                for (int base = 0; base < cnt; base += 32) {
                    const int i = base + lane;
                    const float c = (i < cnt) ? s_cand[i] : NEG;
                    const bool keep = (i < cnt) && (c > tau0);
                    const unsigned bal = __ballot_sync(0xffffffffu, keep);
                    if (!keep && i < cnt) gv = fmaxf(gv, c);
                    const int pos = m2 + __popc(bal & ((1u << lane) - 1u));
                    if (keep) s_cand[pos] = c;     // pos <= i: in-place safe
                    m2 += __popc(bal);
                }
                __syncwarp();
                #pragma unroll
                for (int o = 16; o; o >>= 1)
                    gv = fmaxf(gv, __shfl_xor_sync(0xffffffffu, gv, o));

                float tl = tau0;
                int   kp = -1;
                int   kF = 1; float SF = 0.0f; float vcF = NEG;
                for (int itr = 0; itr < 64; ++itr) {
                    int k = 0; float S = 0.0f; float vc = NEG;
                    for (int i = lane; i < m2; i += 32) {
                        const float c = s_cand[i];
                        if (c > tl) { k++; S += c; } else vc = fmaxf(vc, c);
                    }
                    #pragma unroll
                    for (int o = 16; o; o >>= 1) {
                        k += __shfl_xor_sync(0xffffffffu, k, o);
                        S += __shfl_xor_sync(0xffffffffu, S, o);
                        vc = fmaxf(vc, __shfl_xor_sync(0xffffffffu, vc, o));
                    }
                    kF = k; SF = S; vcF = vc;
                    if (k == kp) break;            // support fixed point
                    kp = k;
                    tl = (S - 1.0f) / (float)k;
                }
                // reference quirk: cs[k_max] = S + max{z <= tau_final}
                const float vfin = fmaxf(vcF, gv);
                const float vt = (vfin > -1e29f) ? vfin : 0.0f;
                if (lane == 0) s_tauref = (SF + vt - 1.0f) / (float)kF;
            }
            __syncthreads();               // B4: tau_ref published
            tau_ref = s_tauref;
        } else {
            // ---- fallback: block-wide Newton over register data ----
            float rm = s_f[lane & 31];
            #pragma unroll
            for (int o = 16; o; o >>= 1)
                rm = fmaxf(rm, __shfl_xor_sync(0xffffffffu, rm, o));
            float tau = rm - 1.0f;
            int kprev = -1;
            tau_ref = 0.0f;
            for (int fit = 0; fit < 64; ++fit) {
                int k = 0; float S = 0.0f; float v = NEG;
                #pragma unroll
                for (int j = 0; j < VPT; ++j) {
                    float c;
                    c = r[j].x; if (c > tau) { k++; S += c; } else v = fmaxf(v, c);
                    c = r[j].y; if (c > tau) { k++; S += c; } else v = fmaxf(v, c);
                    c = r[j].z; if (c > tau) { k++; S += c; } else v = fmaxf(v, c);
                    c = r[j].w; if (c > tau) { k++; S += c; } else v = fmaxf(v, c);
                }
                #pragma unroll
                for (int o = 16; o; o >>= 1) {
                    k += __shfl_xor_sync(0xffffffffu, k, o);
                    S += __shfl_xor_sync(0xffffffffu, S, o);
                    v  = fmaxf(v, __shfl_xor_sync(0xffffffffu, v, o));
                }
                if (lane == 0) { s_i[wid] = k; s_h[wid] = S; s_g[wid] = v; }
                __syncthreads();
                if (tid < 32) {
                    int kk = s_i[tid]; float SS = s_h[tid]; float vv = s_g[tid];
                    #pragma unroll
                    for (int o = 16; o; o >>= 1) {
                        kk += __shfl_xor_sync(0xffffffffu, kk, o);
                        SS += __shfl_xor_sync(0xffffffffu, SS, o);
                        vv  = fmaxf(vv, __shfl_xor_sync(0xffffffffu, vv, o));
                    }
                    if (tid == 0) { s_bK = kk; s_bS = SS; s_bV = vv; }
                }
                __syncthreads();
                const int   K  = s_bK;
                const float Sa = s_bS;
                const float Va = s_bV;
                if (K == kprev || fit == 63) {
                    const float vt = (Va > -1e29f) ? Va : 0.0f;
                    tau_ref = (Sa + vt - 1.0f) / (float)K;
                    break;
                }
                kprev = K;
                tau = (Sa - 1.0f) / (float)K;
                __syncthreads();
            }
        }
        if (tid == 0) s_cnt = 0;           // ordered before next row's B1

        // ---- deferred epilogue: only candidate float4s (+ redo guard) ----
        const bool redoL = (tau_ref < thL);    // theoretical v<0 safety
        const bool redoU = (tau_ref < thU);
        #pragma unroll
        for (int j = 0; j < VPH; ++j) {
            const int f = tid + j * TPB;
            if (f < NVH_ && (redoL || ((dmask >> j) & 1u)))
                __stcs(&orow[f], ep4(r[j], tau_ref));
        }
        #pragma unroll
        for (int j = 0; j < VPH; ++j) {
            const int f = tid + j * TPB;
            if (f < NVH_ && (redoU || ((dmask >> (VPH + j)) & 1u)))
                __stcs(&orow[NVH_ + f], ep4(r[VPH + j], tau_ref));
        }
    }
}

extern "C" void kernel_launch(void* const* d_in, const int* in_sizes, int n_in,
                              void* d_out, int out_size) {
    const float* z = (const float*)d_in[0];
    float* out = (float*)d_out;
    const int rows = in_sizes[0] / NC;

    int dev = 0, sms = 148;
    cudaGetDevice(&dev);
    cudaDeviceGetAttribute(&sms, cudaDevAttrMultiProcessorCount, dev);
    cudaFuncSetAttribute(entmax_kernel,
                         cudaFuncAttributeMaxDynamicSharedMemorySize,
                         8000 * 16);

    const int grid = (rows < sms) ? rows : sms;
    entmax_kernel<<<grid, TPB, 8000 * 16>>>(z, out, rows, grid);
}

// round 14
// speedup vs baseline: 1.1135x; 1.1135x over previous
#include <cuda_runtime.h>
#include <cstdint>

// Entmax (alpha=1.5) per row, B=2048 x N=32000 fp32.
// v13 = v9 (persistent CTA, single 125 KB smem buffer, in-place half-row TMA
// re-arm, chunked bulk copies, warp-0 Newton, contiguous branch-skip
// epilogue) + per-warp-threshold filtering:
//   each warp filters its registers at warpmax_half-1 (<= rowmax-1 <= tau*)
//   right after each half's copy -- no block max barrier in the chain, and
//   the lower half is filtered while the upper half's TMA is in flight.
//   Warp 0 prunes the pool to > rowmax-1 (ballot compaction; pruned values
//   fold into the reject-max) before Newton. v12 lesson applied: NO store
//   fusion, NO masked epilogue -- stores stay clean and contiguous.

#define NC        32000
#define NVH_      4000           // float4 per half
#define TPB       1024
#define VPH       4
#define VPT       8
#define CAP       1024
#define NEG       (-1e30f)
#define HALF_BYTES 64000
#define CHUNKS    4
#define CHUNK_B   (HALF_BYTES / CHUNKS)

__device__ __forceinline__ uint32_t smem_u32(const void* p) {
    uint32_t a;
    asm("{ .reg .u64 t; cvta.to.shared.u64 t, %1; cvt.u32.u64 %0, t; }"
        : "=r"(a) : "l"(p));
    return a;
}
__device__ __forceinline__ void mbar_init(uint32_t a, uint32_t cnt) {
    asm volatile("mbarrier.init.shared.b64 [%0], %1;" :: "r"(a), "r"(cnt) : "memory");
}
__device__ __forceinline__ void mbar_expect_tx(uint32_t a, uint32_t bytes) {
    asm volatile("mbarrier.arrive.expect_tx.shared.b64 _, [%0], %1;"
                 :: "r"(a), "r"(bytes) : "memory");
}
__device__ __forceinline__ void tma_bulk_g2s(uint32_t dst, const void* src,
                                             uint32_t bytes, uint32_t mbar) {
    asm volatile(
        "cp.async.bulk.shared::cta.global.mbarrier::complete_tx::bytes "
        "[%0], [%1], %2, [%3];"
        :: "r"(dst), "l"(src), "r"(bytes), "r"(mbar) : "memory");
}
#define MBAR_WAIT(mbar, parity) do { \
    asm volatile( \
        "{\n\t.reg .pred P1;\n\t" \
        "WAIT_LOOP_%=:\n\t" \
        "mbarrier.try_wait.parity.acquire.cta.shared::cta.b64 P1, [%0], %1, 0x989680;\n\t" \
        "@P1 bra.uni WAIT_DONE_%=;\n\t" \
        "bra.uni WAIT_LOOP_%=;\n\t" \
        "WAIT_DONE_%=:\n\t}" \
        :: "r"(mbar), "r"(parity) : "memory"); \
} while (0)

__device__ __forceinline__ void arm_half(uint32_t mbar, uint32_t dst_base,
                                         const float* src_base) {
    mbar_expect_tx(mbar, HALF_BYTES);
    #pragma unroll
    for (int c = 0; c < CHUNKS; ++c) {
        tma_bulk_g2s(dst_base + c * CHUNK_B,
                     src_base + c * (CHUNK_B / 4), CHUNK_B, mbar);
    }
}

__device__ __forceinline__ float maxtree(float4 v) {
    return fmaxf(fmaxf(v.x, v.y), fmaxf(v.z, v.w));
}

__global__ __launch_bounds__(TPB, 1)
void entmax_kernel(const float* __restrict__ z, float* __restrict__ out,
                   int rows, int gstride) {
    __shared__ float    s_f[32];      // per-warp row max
    __shared__ float    s_g[32];      // per-warp reject max / fallback v
    __shared__ int      s_i[32];      // fallback count partials
    __shared__ float    s_h[32];      // fallback sum partials
    __shared__ float    s_cand[CAP];
    __shared__ int      s_cnt;
    __shared__ float    s_tauref;
    __shared__ int      s_bK;
    __shared__ float    s_bS, s_bV;
    __shared__ uint64_t s_mb[2];
    extern __shared__ float4 s_buf[]; // 8000 float4 = 125 KB

    const int tid  = threadIdx.x;
    const int lane = tid & 31;
    const int wid  = tid >> 5;

    const uint32_t mbL = smem_u32(&s_mb[0]);
    const uint32_t mbH = smem_u32(&s_mb[1]);
    const uint32_t bufL = smem_u32(s_buf);
    const uint32_t bufH = bufL + HALF_BYTES;

    if (tid == 0) { mbar_init(mbL, 1); mbar_init(mbH, 1); s_cnt = 0; }
    __syncthreads();

    const int r0     = blockIdx.x;
    const int myrows = (r0 < rows) ? ((rows - r0 - 1) / gstride + 1) : 0;

    if (tid == 0 && myrows > 0) {
        const float* row0 = z + (long long)r0 * NC;
        arm_half(mbL, bufL, row0);
        arm_half(mbH, bufH, row0 + 4 * NVH_);
    }

    for (int ri = 0; ri < myrows; ++ri) {
        const int row = r0 + ri * gstride;
        const uint32_t par = (uint32_t)(ri & 1);
        const bool have_next = (ri + 1 < myrows);
        const float* nrow = z + (long long)(row + gstride) * NC;

        float4 r[VPT];
        float vmax = NEG;

        // ======== LOWER HALF: wait, copy (fused thread max), arm, filter ====
        MBAR_WAIT(mbL, par);
        float tmL = NEG;
        #pragma unroll
        for (int j = 0; j < VPH; ++j) {
            const int f = tid + j * TPB;
            if (f < NVH_) {
                float4 v = s_buf[f];
                r[j] = v;
                tmL = fmaxf(tmL, maxtree(v));
            } else {
                r[j] = make_float4(NEG, NEG, NEG, NEG);
            }
        }
        __syncthreads();                   // B1: lower reads done
        if (tid == 0) {
            asm volatile("fence.proxy.async.shared::cta;" ::: "memory");
            if (have_next) arm_half(mbL, bufL, nrow);
        }
        float wmL = tmL;
        #pragma unroll
        for (int o = 16; o; o >>= 1)
            wmL = fmaxf(wmL, __shfl_xor_sync(0xffffffffu, wmL, o));
        const float thL = wmL - 1.0f;      // per-warp, <= rowmax-1 <= tau*
        #pragma unroll
        for (int j = 0; j < VPH; ++j) {
            const float4 v = r[j];
            const float m4 = maxtree(v);
            if (m4 > thL) {
                float c;
                c = v.x; if (c > thL) { int p = atomicAdd(&s_cnt, 1); if (p < CAP) s_cand[p] = c; } else vmax = fmaxf(vmax, c);
                c = v.y; if (c > thL) { int p = atomicAdd(&s_cnt, 1); if (p < CAP) s_cand[p] = c; } else vmax = fmaxf(vmax, c);
                c = v.z; if (c > thL) { int p = atomicAdd(&s_cnt, 1); if (p < CAP) s_cand[p] = c; } else vmax = fmaxf(vmax, c);
                c = v.w; if (c > thL) { int p = atomicAdd(&s_cnt, 1); if (p < CAP) s_cand[p] = c; } else vmax = fmaxf(vmax, c);
            } else {
                vmax = fmaxf(vmax, m4);
            }
        }

        // ======== UPPER HALF: wait, copy, arm, filter ========
        MBAR_WAIT(mbH, par);
        float tmU = NEG;
        #pragma unroll
        for (int j = 0; j < VPH; ++j) {
            const int f = tid + j * TPB;
            if (f < NVH_) {
                float4 v = s_buf[NVH_ + f];
                r[VPH + j] = v;
                tmU = fmaxf(tmU, maxtree(v));
            } else {
                r[VPH + j] = make_float4(NEG, NEG, NEG, NEG);
            }
        }
        __syncthreads();                   // B2: upper reads done
        if (tid == 0) {
            asm volatile("fence.proxy.async.shared::cta;" ::: "memory");
            if (have_next) arm_half(mbH, bufH, nrow + 4 * NVH_);
        }
        float wmU = tmU;
        #pragma unroll
        for (int o = 16; o; o >>= 1)
            wmU = fmaxf(wmU, __shfl_xor_sync(0xffffffffu, wmU, o));
        const float thU = wmU - 1.0f;
        #pragma unroll
        for (int j = 0; j < VPH; ++j) {
            const float4 v = r[VPH + j];
            const float m4 = maxtree(v);
            if (m4 > thU) {
                float c;
                c = v.x; if (c > thU) { int p = atomicAdd(&s_cnt, 1); if (p < CAP) s_cand[p] = c; } else vmax = fmaxf(vmax, c);
                c = v.y; if (c > thU) { int p = atomicAdd(&s_cnt, 1); if (p < CAP) s_cand[p] = c; } else vmax = fmaxf(vmax, c);
                c = v.z; if (c > thU) { int p = atomicAdd(&s_cnt, 1); if (p < CAP) s_cand[p] = c; } else vmax = fmaxf(vmax, c);
                c = v.w; if (c > thU) { int p = atomicAdd(&s_cnt, 1); if (p < CAP) s_cand[p] = c; } else vmax = fmaxf(vmax, c);
            } else {
                vmax = fmaxf(vmax, m4);
            }
        }

        // ---- publish per-warp partials ----
        #pragma unroll
        for (int o = 16; o; o >>= 1)
            vmax = fmaxf(vmax, __shfl_xor_sync(0xffffffffu, vmax, o));
        if (lane == 0) { s_f[wid] = fmaxf(wmL, wmU); s_g[wid] = vmax; }
        __syncthreads();                   // B3: pool + partials visible
        const int cnt = s_cnt;
        float tau_ref;

        if (cnt <= CAP) {
            // ---- warp 0: rowmax, prune pool to > rowmax-1, Newton ----
            if (wid == 0) {
                float rm = s_f[lane];
                #pragma unroll
                for (int o = 16; o; o >>= 1)
                    rm = fmaxf(rm, __shfl_xor_sync(0xffffffffu, rm, o));
                const float tau0 = rm - 1.0f;
                float gv = s_g[lane];

                int m2 = 0;
                for (int base = 0; base < cnt; base += 32) {
                    const int i = base + lane;
                    const float c = (i < cnt) ? s_cand[i] : NEG;
                    const bool keep = (i < cnt) && (c > tau0);
                    const unsigned bal = __ballot_sync(0xffffffffu, keep);
                    if (!keep && i < cnt) gv = fmaxf(gv, c);
                    const int pos = m2 + __popc(bal & ((1u << lane) - 1u));
                    if (keep) s_cand[pos] = c;     // pos <= i: in-place safe
                    m2 += __popc(bal);
                }
                __syncwarp();
                #pragma unroll
                for (int o = 16; o; o >>= 1)
                    gv = fmaxf(gv, __shfl_xor_sync(0xffffffffu, gv, o));

                float tl = tau0;
                int   kp = -1;
                int   kF = 1; float SF = 0.0f; float vcF = NEG;
                for (int itr = 0; itr < 64; ++itr) {
                    int k = 0; float S = 0.0f; float vc = NEG;
                    for (int i = lane; i < m2; i += 32) {
                        const float c = s_cand[i];
                        if (c > tl) { k++; S += c; } else vc = fmaxf(vc, c);
                    }
                    #pragma unroll
                    for (int o = 16; o; o >>= 1) {
                        k += __shfl_xor_sync(0xffffffffu, k, o);
                        S += __shfl_xor_sync(0xffffffffu, S, o);
                        vc = fmaxf(vc, __shfl_xor_sync(0xffffffffu, vc, o));
                    }
                    kF = k; SF = S; vcF = vc;
                    if (k == kp) break;            // support fixed point
                    kp = k;
                    tl = (S - 1.0f) / (float)k;
                }
                // reference quirk: cs[k_max] = S + max{z <= tau_final}
                const float vfin = fmaxf(vcF, gv);
                const float vt = (vfin > -1e29f) ? vfin : 0.0f;
                if (lane == 0) s_tauref = (SF + vt - 1.0f) / (float)kF;
            }
            __syncthreads();               // B4: tau_ref published
            tau_ref = s_tauref;
        } else {
            // ---- fallback: block-wide Newton over register data ----
            float rm = s_f[lane];
            #pragma unroll
            for (int o = 16; o; o >>= 1)
                rm = fmaxf(rm, __shfl_xor_sync(0xffffffffu, rm, o));
            float tau = rm - 1.0f;
            int kprev = -1;
            tau_ref = 0.0f;
            for (int fit = 0; fit < 64; ++fit) {
                int k = 0; float S = 0.0f; float v = NEG;
                #pragma unroll
                for (int j = 0; j < VPT; ++j) {
                    float c;
                    c = r[j].x; if (c > tau) { k++; S += c; } else v = fmaxf(v, c);
                    c = r[j].y; if (c > tau) { k++; S += c; } else v = fmaxf(v, c);
                    c = r[j].z; if (c > tau) { k++; S += c; } else v = fmaxf(v, c);
                    c = r[j].w; if (c > tau) { k++; S += c; } else v = fmaxf(v, c);
                }
                #pragma unroll
                for (int o = 16; o; o >>= 1) {
                    k += __shfl_xor_sync(0xffffffffu, k, o);
                    S += __shfl_xor_sync(0xffffffffu, S, o);
                    v  = fmaxf(v, __shfl_xor_sync(0xffffffffu, v, o));
                }
                if (lane == 0) { s_i[wid] = k; s_h[wid] = S; s_g[wid] = v; }
                __syncthreads();
                if (tid < 32) {
                    int kk = s_i[tid]; float SS = s_h[tid]; float vv = s_g[tid];
                    #pragma unroll
                    for (int o = 16; o; o >>= 1) {
                        kk += __shfl_xor_sync(0xffffffffu, kk, o);
                        SS += __shfl_xor_sync(0xffffffffu, SS, o);
                        vv  = fmaxf(vv, __shfl_xor_sync(0xffffffffu, vv, o));
                    }
                    if (tid == 0) { s_bK = kk; s_bS = SS; s_bV = vv; }
                }
                __syncthreads();
                const int   K  = s_bK;
                const float Sa = s_bS;
                const float Va = s_bV;
                if (K == kprev || fit == 63) {
                    const float vt = (Va > -1e29f) ? Va : 0.0f;
                    tau_ref = (Sa + vt - 1.0f) / (float)K;
                    break;
                }
                kprev = K;
                tau = (Sa - 1.0f) / (float)K;
                __syncthreads();
            }
        }
        if (tid == 0) s_cnt = 0;           // ordered before next row's filter
                                           // by this row's B1 barrier

        // ---- output: v9's contiguous branch-skip epilogue, untouched ----
        float4* orow = (float4*)(out + (long long)row * NC);
        #pragma unroll
        for (int h = 0; h < 2; ++h) {
            #pragma unroll
            for (int j = 0; j < VPH; ++j) {
                const int f = tid + j * TPB;
                if (f < NVH_) {
                    const float4 v = r[h * VPH + j];
                    float a = v.x - tau_ref, bb = v.y - tau_ref;
                    float c = v.z - tau_ref, d = v.w - tau_ref;
                    float4 o;
                    if (fmaxf(fmaxf(a, bb), fmaxf(c, d)) > 0.0f) {
                        a = fmaxf(a, 0.0f); bb = fmaxf(bb, 0.0f);
                        c = fmaxf(c, 0.0f); d = fmaxf(d, 0.0f);
                        o.x = a * sqrtf(a);  o.y = bb * sqrtf(bb);
                        o.z = c * sqrtf(c);  o.w = d * sqrtf(d);
                    } else {
                        o.x = 0.0f; o.y = 0.0f; o.z = 0.0f; o.w = 0.0f;
                    }
                    __stcs(&orow[h * NVH_ + f], o);
                }
            }
        }
    }
}

extern "C" void kernel_launch(void* const* d_in, const int* in_sizes, int n_in,
                              void* d_out, int out_size) {
    const float* z = (const float*)d_in[0];
    float* out = (float*)d_out;
    const int rows = in_sizes[0] / NC;

    int dev = 0, sms = 148;
    cudaGetDevice(&dev);
    cudaDeviceGetAttribute(&sms, cudaDevAttrMultiProcessorCount, dev);
    cudaFuncSetAttribute(entmax_kernel,
                         cudaFuncAttributeMaxDynamicSharedMemorySize,
                         8000 * 16);

    const int grid = (rows < sms) ? rows : sms;
    entmax_kernel<<<grid, TPB, 8000 * 16>>>(z, out, rows, grid);
}

// round 15
// speedup vs baseline: 1.7643x; 1.5844x over previous
#include <cuda_runtime.h>
#include <cstdint>

// Entmax (alpha=1.5) per row, B=2048 x N=32000 fp32.
// v14 = v9 EXACTLY (persistent CTA, single 125 KB smem buffer, in-place
// half-row TMA re-arm, chunked bulk copies, block max reduce, max-tree
// filter, warp-0 Newton) with ONE change: the write stream.
//   - Right after the row is register-resident: unconditional, uniform,
//     contiguous zero-store pass (always a correct base; ~99.95% of the
//     output). Issues 128 KB of stores that overlap reduce+filter+Newton.
//   - After tau: sparse overwrite of only float4s with maxtree > tau_ref
//     (exactly the nonzero outputs; same-thread same-address ordering).
// v12/v13 lesson honored: the copy and filter sweeps are byte-identical v9.

#define NC        32000
#define NVH_      4000           // float4 per half
#define TPB       1024
#define VPH       4
#define VPT       8
#define CAP       1024
#define NEG       (-1e30f)
#define HALF_BYTES 64000
#define CHUNKS    4
#define CHUNK_B   (HALF_BYTES / CHUNKS)

__device__ __forceinline__ uint32_t smem_u32(const void* p) {
    uint32_t a;
    asm("{ .reg .u64 t; cvta.to.shared.u64 t, %1; cvt.u32.u64 %0, t; }"
        : "=r"(a) : "l"(p));
    return a;
}
__device__ __forceinline__ void mbar_init(uint32_t a, uint32_t cnt) {
    asm volatile("mbarrier.init.shared.b64 [%0], %1;" :: "r"(a), "r"(cnt) : "memory");
}
__device__ __forceinline__ void mbar_expect_tx(uint32_t a, uint32_t bytes) {
    asm volatile("mbarrier.arrive.expect_tx.shared.b64 _, [%0], %1;"
                 :: "r"(a), "r"(bytes) : "memory");
}
__device__ __forceinline__ void tma_bulk_g2s(uint32_t dst, const void* src,
                                             uint32_t bytes, uint32_t mbar) {
    asm volatile(
        "cp.async.bulk.shared::cta.global.mbarrier::complete_tx::bytes "
        "[%0], [%1], %2, [%3];"
        :: "r"(dst), "l"(src), "r"(bytes), "r"(mbar) : "memory");
}
#define MBAR_WAIT(mbar, parity) do { \
    asm volatile( \
        "{\n\t.reg .pred P1;\n\t" \
        "WAIT_LOOP_%=:\n\t" \
        "mbarrier.try_wait.parity.acquire.cta.shared::cta.b64 P1, [%0], %1, 0x989680;\n\t" \
        "@P1 bra.uni WAIT_DONE_%=;\n\t" \
        "bra.uni WAIT_LOOP_%=;\n\t" \
        "WAIT_DONE_%=:\n\t}" \
        :: "r"(mbar), "r"(parity) : "memory"); \
} while (0)

__device__ __forceinline__ void arm_half(uint32_t mbar, uint32_t dst_base,
                                         const float* src_base) {
    mbar_expect_tx(mbar, HALF_BYTES);
    #pragma unroll
    for (int c = 0; c < CHUNKS; ++c) {
        tma_bulk_g2s(dst_base + c * CHUNK_B,
                     src_base + c * (CHUNK_B / 4), CHUNK_B, mbar);
    }
}

__device__ __forceinline__ float maxtree(float4 v) {
    return fmaxf(fmaxf(v.x, v.y), fmaxf(v.z, v.w));
}

__global__ __launch_bounds__(TPB, 1)
void entmax_kernel(const float* __restrict__ z, float* __restrict__ out,
                   int rows, int gstride) {
    __shared__ float    s_f[32];      // max partials
    __shared__ float    s_g[32];      // vmax partials
    __shared__ int      s_i[32];      // fallback count partials
    __shared__ float    s_h[32];      // fallback sum partials
    __shared__ float    s_cand[CAP];
    __shared__ int      s_cnt;
    __shared__ float    s_tauref;
    __shared__ int      s_bK;
    __shared__ float    s_bS, s_bV;
    __shared__ uint64_t s_mb[2];
    extern __shared__ float4 s_buf[]; // 8000 float4 = 125 KB

    const int tid  = threadIdx.x;
    const int lane = tid & 31;
    const int wid  = tid >> 5;

    const uint32_t mbL = smem_u32(&s_mb[0]);
    const uint32_t mbH = smem_u32(&s_mb[1]);
    const uint32_t bufL = smem_u32(s_buf);
    const uint32_t bufH = bufL + HALF_BYTES;

    if (tid == 0) { mbar_init(mbL, 1); mbar_init(mbH, 1); }
    __syncthreads();

    const int r0     = blockIdx.x;
    const int myrows = (r0 < rows) ? ((rows - r0 - 1) / gstride + 1) : 0;

    if (tid == 0 && myrows > 0) {
        const float* row0 = z + (long long)r0 * NC;
        arm_half(mbL, bufL, row0);
        arm_half(mbH, bufH, row0 + 4 * NVH_);
    }

    for (int ri = 0; ri < myrows; ++ri) {
        const int row = r0 + ri * gstride;
        const uint32_t par = (uint32_t)(ri & 1);
        const bool have_next = (ri + 1 < myrows);
        const float* nrow = z + (long long)(row + gstride) * NC;
        float4* orow = (float4*)(out + (long long)row * NC);

        float4 r[VPT];
        float lmax = NEG;

        // ---- lower half: wait, copy (fused max), re-arm for next row ----
        MBAR_WAIT(mbL, par);
        #pragma unroll
        for (int j = 0; j < VPH; ++j) {
            const int f = tid + j * TPB;
            if (f < NVH_) {
                float4 v = s_buf[f];
                r[j] = v;
                lmax = fmaxf(lmax, maxtree(v));
            } else {
                r[j] = make_float4(NEG, NEG, NEG, NEG);
            }
        }
        __syncthreads();                   // lower-half reads done
        if (tid == 0) {
            asm volatile("fence.proxy.async.shared::cta;" ::: "memory");
            if (have_next) arm_half(mbL, bufL, nrow);
        }

        // ---- upper half: wait, copy (fused max), re-arm ----
        MBAR_WAIT(mbH, par);
        #pragma unroll
        for (int j = 0; j < VPH; ++j) {
            const int f = tid + j * TPB;
            if (f < NVH_) {
                float4 v = s_buf[NVH_ + f];
                r[VPH + j] = v;
                lmax = fmaxf(lmax, maxtree(v));
            } else {
                r[VPH + j] = make_float4(NEG, NEG, NEG, NEG);
            }
        }
        __syncthreads();                   // upper-half reads done
        if (tid == 0) {
            asm volatile("fence.proxy.async.shared::cta;" ::: "memory");
            if (have_next) arm_half(mbH, bufH, nrow + 4 * NVH_);
            s_cnt = 0;
        }

        // ---- EARLY ZERO PASS: unconditional, uniform, contiguous.
        //      Always a correct base; overlaps reduce+filter+Newton. ----
        {
            const float4 z4 = make_float4(0.f, 0.f, 0.f, 0.f);
            #pragma unroll
            for (int h = 0; h < 2; ++h) {
                #pragma unroll
                for (int j = 0; j < VPH; ++j) {
                    const int f = tid + j * TPB;
                    if (f < NVH_) __stcs(&orow[h * NVH_ + f], z4);
                }
            }
        }

        // ---- max reduce: publish once; every warp finishes privately ----
        #pragma unroll
        for (int o = 16; o; o >>= 1)
            lmax = fmaxf(lmax, __shfl_xor_sync(0xffffffffu, lmax, o));
        if (lane == 0) s_f[wid] = lmax;
        __syncthreads();                   // partials + s_cnt=0 visible
        float m = s_f[lane];
        #pragma unroll
        for (int o = 16; o; o >>= 1)
            m = fmaxf(m, __shfl_xor_sync(0xffffffffu, m, o));
        const float tau0 = m - 1.0f;

        // ---- filter via max-tree pre-test (v9 verbatim) ----
        float vmax = NEG;
        #pragma unroll
        for (int j = 0; j < VPT; ++j) {
            const float4 v = r[j];
            const float m4 = maxtree(v);
            if (m4 > tau0) {
                float c;
                c = v.x; if (c > tau0) { int p = atomicAdd(&s_cnt, 1); if (p < CAP) s_cand[p] = c; } else vmax = fmaxf(vmax, c);
                c = v.y; if (c > tau0) { int p = atomicAdd(&s_cnt, 1); if (p < CAP) s_cand[p] = c; } else vmax = fmaxf(vmax, c);
                c = v.z; if (c > tau0) { int p = atomicAdd(&s_cnt, 1); if (p < CAP) s_cand[p] = c; } else vmax = fmaxf(vmax, c);
                c = v.w; if (c > tau0) { int p = atomicAdd(&s_cnt, 1); if (p < CAP) s_cand[p] = c; } else vmax = fmaxf(vmax, c);
            } else {
                vmax = fmaxf(vmax, m4);
            }
        }
        #pragma unroll
        for (int o = 16; o; o >>= 1)
            vmax = fmaxf(vmax, __shfl_xor_sync(0xffffffffu, vmax, o));
        if (lane == 0) s_g[wid] = vmax;
        __syncthreads();                   // cand/cnt/vmax visible
        const int cnt = s_cnt;
        float tau_ref;

        if (cnt <= CAP) {
            // ---- warp 0 only: private vmax reduce + Newton (v9 verbatim) --
            if (wid == 0) {
                float gv = s_g[lane];
                #pragma unroll
                for (int o = 16; o; o >>= 1)
                    gv = fmaxf(gv, __shfl_xor_sync(0xffffffffu, gv, o));

                float tl = tau0;
                int   kp = -1;
                int   kF = 1; float SF = 0.0f; float vcF = NEG;
                for (int itr = 0; itr < 64; ++itr) {
                    int k = 0; float S = 0.0f; float vc = NEG;
                    for (int i = lane; i < cnt; i += 32) {
                        const float c = s_cand[i];
                        if (c > tl) { k++; S += c; } else vc = fmaxf(vc, c);
                    }
                    #pragma unroll
                    for (int o = 16; o; o >>= 1) {
                        k += __shfl_xor_sync(0xffffffffu, k, o);
                        S += __shfl_xor_sync(0xffffffffu, S, o);
                        vc = fmaxf(vc, __shfl_xor_sync(0xffffffffu, vc, o));
                    }
                    kF = k; SF = S; vcF = vc;
                    if (k == kp) break;    // support fixed point
                    kp = k;
                    tl = (S - 1.0f) / (float)k;
                }
                // reference quirk: cs[k_max] = S + max{z <= tau_final}
                const float vfin = fmaxf(vcF, gv);
                const float vt = (vfin > -1e29f) ? vfin : 0.0f;
                if (lane == 0) s_tauref = (SF + vt - 1.0f) / (float)kF;
            }
            __syncthreads();               // tau_ref published
            tau_ref = s_tauref;
        } else {
            // ---- fallback: block-wide Newton over register data ----
            float tau = tau0;
            int kprev = -1;
            tau_ref = 0.0f;
            for (int fit = 0; fit < 64; ++fit) {
                int k = 0; float S = 0.0f; float v = NEG;
                #pragma unroll
                for (int j = 0; j < VPT; ++j) {
                    float c;
                    c = r[j].x; if (c > tau) { k++; S += c; } else v = fmaxf(v, c);
                    c = r[j].y; if (c > tau) { k++; S += c; } else v = fmaxf(v, c);
                    c = r[j].z; if (c > tau) { k++; S += c; } else v = fmaxf(v, c);
                    c = r[j].w; if (c > tau) { k++; S += c; } else v = fmaxf(v, c);
                }
                #pragma unroll
                for (int o = 16; o; o >>= 1) {
                    k += __shfl_xor_sync(0xffffffffu, k, o);
                    S += __shfl_xor_sync(0xffffffffu, S, o);
                    v  = fmaxf(v, __shfl_xor_sync(0xffffffffu, v, o));
                }
                if (lane == 0) { s_i[wid] = k; s_h[wid] = S; s_g[wid] = v; }
                __syncthreads();
                if (tid < 32) {
                    int kk = s_i[tid]; float SS = s_h[tid]; float vv = s_g[tid];
                    #pragma unroll
                    for (int o = 16; o; o >>= 1) {
                        kk += __shfl_xor_sync(0xffffffffu, kk, o);
                        SS += __shfl_xor_sync(0xffffffffu, SS, o);
                        vv  = fmaxf(vv, __shfl_xor_sync(0xffffffffu, vv, o));
                    }
                    if (tid == 0) { s_bK = kk; s_bS = SS; s_bV = vv; }
                }
                __syncthreads();
                const int   K  = s_bK;
                const float Sa = s_bS;
                const float Va = s_bV;
                if (K == kprev || fit == 63) {
                    const float vt = (Va > -1e29f) ? Va : 0.0f;
                    tau_ref = (Sa + vt - 1.0f) / (float)K;
                    break;
                }
                kprev = K;
                tau = (Sa - 1.0f) / (float)K;
                __syncthreads();
            }
        }

        // ---- SPARSE OVERWRITE: only float4s containing nonzero outputs
        //      (elem > 0 iff z > tau_ref iff maxtree > tau_ref). Same thread
        //      wrote the zero base -> program order fixes final value. ----
        #pragma unroll
        for (int h = 0; h < 2; ++h) {
            #pragma unroll
            for (int j = 0; j < VPH; ++j) {
                const int f = tid + j * TPB;
                if (f < NVH_) {
                    const float4 v = r[h * VPH + j];
                    if (maxtree(v) > tau_ref) {
                        float a = fmaxf(v.x - tau_ref, 0.0f);
                        float b = fmaxf(v.y - tau_ref, 0.0f);
                        float c = fmaxf(v.z - tau_ref, 0.0f);
                        float d = fmaxf(v.w - tau_ref, 0.0f);
                        float4 o;
                        o.x = a * sqrtf(a);  o.y = b * sqrtf(b);
                        o.z = c * sqrtf(c);  o.w = d * sqrtf(d);
                        __stcs(&orow[h * NVH_ + f], o);
                    }
                }
            }
        }
    }
}

extern "C" void kernel_launch(void* const* d_in, const int* in_sizes, int n_in,
                              void* d_out, int out_size) {
    const float* z = (const float*)d_in[0];
    float* out = (float*)d_out;
    const int rows = in_sizes[0] / NC;

    int dev = 0, sms = 148;
    cudaGetDevice(&dev);
    cudaDeviceGetAttribute(&sms, cudaDevAttrMultiProcessorCount, dev);
    cudaFuncSetAttribute(entmax_kernel,
                         cudaFuncAttributeMaxDynamicSharedMemorySize,
                         8000 * 16);

    const int grid = (rows < sms) ? rows : sms;
    entmax_kernel<<<grid, TPB, 8000 * 16>>>(z, out, rows, grid);
}